// round 5
// baseline (speedup 1.0000x reference)
#include <cuda_runtime.h>
#include <cuda_bf16.h>
#include <math.h>
#include <cstdint>

#define B_  2
#define S_  2048
#define D_  1024
#define H_  16
#define HD_ 64
#define M_  (B_ * S_)
#define BH_ (B_ * H_)
#define MAXLEN_ 5000

// ---------------- scratch (device globals) ----------------------------------
__device__ float g_xpe[M_ * D_];
__device__ float g_q[M_ * D_];
__device__ float g_k[M_ * D_];
__device__ float g_v[M_ * D_];
__device__ float g_ctx[M_ * D_];
__device__ float g_scores[(size_t)BH_ * S_ * S_];
__device__ float g_w[4][D_ * D_];

// ---------------- helpers ----------------------------------------------------
__device__ __forceinline__ uint32_t smem_u32(const void* p) {
    uint32_t a;
    asm("{ .reg .u64 t; cvta.to.shared.u64 t, %1; cvt.u32.u64 %0, t; }"
        : "=r"(a) : "l"(p));
    return a;
}
__device__ __forceinline__ float f2tf_f(float f) {
    uint32_t r;
    asm("cvt.rna.tf32.f32 %0, %1;" : "=r"(r) : "f"(f));
    return __uint_as_float(r);
}
// within-8 k permutation: k -> 2*(k&3) | (k>>2)
__device__ __forceinline__ int pcol(int k) {
    return (k & ~7) | (((k & 3) << 1) | ((k >> 2) & 1));
}
__device__ __forceinline__ void mma8(float* c, const uint32_t* a, const uint32_t* b) {
    asm volatile(
        "mma.sync.aligned.m16n8k8.row.col.f32.tf32.tf32.f32 "
        "{%0,%1,%2,%3}, {%4,%5,%6,%7}, {%8,%9}, {%0,%1,%2,%3};"
        : "+f"(c[0]), "+f"(c[1]), "+f"(c[2]), "+f"(c[3])
        : "r"(a[0]), "r"(a[1]), "r"(a[2]), "r"(a[3]), "r"(b[0]), "r"(b[1]));
}
#define CP16(dst, src) \
    asm volatile("cp.async.cg.shared.global [%0], [%1], 16;" \
        :: "r"(dst), "l"(src) : "memory")
#define CP_COMMIT() asm volatile("cp.async.commit_group;" ::: "memory")

// ---------------- weight prep: tf32-round + k-permute, all 4 weights ---------
__global__ __launch_bounds__(256) void wprep_kernel(
    const float* __restrict__ w0, const float* __restrict__ w1,
    const float* __restrict__ w2, const float* __restrict__ w3)
{
    const float* srcs[4] = {w0, w1, w2, w3};
    const float* src = srcs[blockIdx.y];
    float* dst = g_w[blockIdx.y];
    int base = (blockIdx.x * 256 + threadIdx.x) * 4;
    #pragma unroll
    for (int i = 0; i < 4; i++) {
        int idx = base + i;
        int n = idx >> 10, k = idx & 1023;
        dst[(n << 10) | pcol(k)] = f2tf_f(src[idx]);
    }
}

// ---------------- kernel 1: x + PE, tf32-rounded, k-permuted -----------------
__global__ __launch_bounds__(256) void pe_kernel(
    const float* __restrict__ x, const float* __restrict__ rel,
    const float* __restrict__ alpha_p, float* __restrict__ xpe)
{
    const int bs = blockIdx.x;
    const int s  = bs & (S_ - 1);
    const float alpha = alpha_p[0];
    const float beta  = 1.0f - alpha;
    const size_t base  = (size_t)bs * D_;
    const size_t rbase = (size_t)(MAXLEN_ - S_ + s) * D_;
    const float kC = (float)(-9.210340371976184 / 1024.0);

    #pragma unroll
    for (int t = 0; t < 2; t++) {
        int p  = threadIdx.x * 2 + t;
        int d0 = p * 2;
        float divv = expf((float)d0 * kC);
        float ang  = (float)s * divv;
        float sn, cs;
        sincosf(ang, &sn, &cs);
        float m0 = alpha * sn + beta * rel[rbase + d0];
        float m1 = alpha * cs + beta * rel[rbase + d0 + 1];
        xpe[base + pcol(d0)]     = f2tf_f(x[base + d0]     + m0);
        xpe[base + pcol(d0 + 1)] = f2tf_f(x[base + d0 + 1] + m1);
    }
}

// ---------------- tf32 mma.sync GEMM, 4 warps x (64x64), 3-stage pipeline ----
// MODE 0: O-proj   MODE 1: Q/K proj (scatter+perm)   MODE 4: V proj (scatter)
// MODE 2: QK^T per z     MODE 3: PV per z (V transposed on load)
template<int MODE>
__global__ __launch_bounds__(128) void mma_gemm(
    const float* __restrict__ A, const float* __restrict__ Bm,
    const float* __restrict__ bias, float* __restrict__ C, float scale)
{
    constexpr int BM = 128, BK = 16;
    constexpr int BN   = (MODE == 3) ? 64 : 128;
    constexpr int WN   = (MODE == 3) ? 32 : 64;      // warp tile N
    constexpr int NF   = WN / 8;                     // 4 or 8
    constexpr int KTOT = (MODE == 2) ? 64 : ((MODE == 3) ? 2048 : 1024);
    constexpr int LDA  = (MODE == 2) ? 64 : ((MODE == 3) ? 2048 : 1024);
    constexpr int LDB  = (MODE == 2) ? 64 : 1024;
    constexpr int NK   = KTOT / BK;
    constexpr int SA   = 24;                         // 16 + 8 pad, conflict-free v2
    constexpr int ASZ  = BM * SA;
    constexpr int BSZ  = BN * SA;
    constexpr int STG  = ASZ + BSZ;

    extern __shared__ __align__(16) float sm[];
    const int tid  = threadIdx.x;
    const int wid  = tid >> 5, lane = tid & 31;
    const int gid  = lane >> 2, tig = lane & 3;
    const int wm   = wid & 1;                        // 2 warps along M
    const int wn   = wid >> 1;                       // 2 warps along N

    const int bm = blockIdx.y * BM;
    const int bn = blockIdx.x * BN;
    const int z  = blockIdx.z;

    const float* Ab = A  + ((MODE == 2) ? (size_t)z * S_ * HD_
                          : (MODE == 3) ? (size_t)z * S_ * S_ : (size_t)0);
    const float* Bb = Bm + ((MODE == 2 || MODE == 3) ? (size_t)z * S_ * HD_ : (size_t)0);

    float acc[4][NF][4];
    #pragma unroll
    for (int i = 0; i < 4; i++)
        #pragma unroll
        for (int j = 0; j < NF; j++)
            #pragma unroll
            for (int r = 0; r < 4; r++) acc[i][j][r] = 0.0f;

    auto load_stage = [&](int kc, int buf) {
        float* sA = sm + buf * STG;
        float* sB = sA + ASZ;
        const float* Ap = Ab + (size_t)bm * LDA + kc * BK;
        uint32_t sAu = smem_u32(sA);
        #pragma unroll
        for (int i = 0; i < 4; i++) {                // 128 rows x 4 chunks / 128 thr
            int f = tid + i * 128;
            int m = f >> 2, c = f & 3;
            CP16(sAu + (uint32_t)(m * SA + c * 4) * 4, Ap + (size_t)m * LDA + c * 4);
        }
        if (MODE != 3) {
            const float* Bp = Bb + (size_t)bn * LDB + kc * BK;
            uint32_t sBu = smem_u32(sB);
            #pragma unroll
            for (int i = 0; i < 4; i++) {
                int f = tid + i * 128;
                int n = f >> 2, c = f & 3;
                CP16(sBu + (uint32_t)(n * SA + c * 4) * 4, Bp + (size_t)n * LDB + c * 4);
            }
        } else {
            // V transpose: sB[n][perm(k)] = V[kc*16+k][n] (v pre-rounded)
            #pragma unroll
            for (int i = 0; i < 8; i++) {            // 64*16/128
                int idx = tid + i * 128;
                int n = idx & 63, k = idx >> 6;
                sB[n * SA + pcol(k)] = Bb[(size_t)(kc * BK + k) * HD_ + n];
            }
        }
        CP_COMMIT();
    };

    load_stage(0, 0);
    load_stage(1, 1);

    int buf = 0;
    for (int kc = 0; kc < NK; kc++) {
        asm volatile("cp.async.wait_group 1;" ::: "memory");
        __syncthreads();

        const float* sA = sm + buf * STG;
        const float* sB = sA + ASZ;

        #pragma unroll
        for (int kk = 0; kk < BK; kk += 8) {
            uint32_t a[4][4];
            #pragma unroll
            for (int mf = 0; mf < 4; mf++) {
                const float* pa = sA + (wm * 64 + mf * 16 + gid) * SA + kk + 2 * tig;
                float2 w0 = *reinterpret_cast<const float2*>(pa);
                float2 w1 = *reinterpret_cast<const float2*>(pa + 8 * SA);
                a[mf][0] = __float_as_uint(w0.x);
                a[mf][1] = __float_as_uint(w1.x);
                a[mf][2] = __float_as_uint(w0.y);
                a[mf][3] = __float_as_uint(w1.y);
            }
            uint32_t b[NF][2];
            #pragma unroll
            for (int nf = 0; nf < NF; nf++) {
                float2 w = *reinterpret_cast<const float2*>(
                    sB + (wn * WN + nf * 8 + gid) * SA + kk + 2 * tig);
                b[nf][0] = __float_as_uint(w.x);
                b[nf][1] = __float_as_uint(w.y);
            }
            #pragma unroll
            for (int mf = 0; mf < 4; mf++)
                #pragma unroll
                for (int nf = 0; nf < NF; nf++)
                    mma8(acc[mf][nf], a[mf], b[nf]);
        }

        if (kc + 2 < NK) load_stage(kc + 2, (kc + 2) % 3);
        else             CP_COMMIT();                 // keep group accounting
        buf = (buf + 1 == 3) ? 0 : buf + 1;
    }

    // ---- epilogue -----------------------------------------------------------
    #pragma unroll
    for (int mf = 0; mf < 4; mf++) {
        #pragma unroll
        for (int r = 0; r < 2; r++) {
            int m = bm + wm * 64 + mf * 16 + gid + r * 8;
            #pragma unroll
            for (int nf = 0; nf < NF; nf++) {
                int n = bn + wn * WN + nf * 8 + 2 * tig;
                float v0 = acc[mf][nf][r * 2 + 0] * scale;
                float v1 = acc[mf][nf][r * 2 + 1] * scale;
                if (MODE == 0) {
                    v0 += bias[n]; v1 += bias[n + 1];
                    *reinterpret_cast<float2*>(&C[(size_t)m * D_ + n]) =
                        make_float2(v0, v1);
                } else if (MODE == 1) {
                    v0 = f2tf_f(v0 + bias[n]);
                    v1 = f2tf_f(v1 + bias[n + 1]);
                    int b = m >> 11, s = m & (S_ - 1);
                    size_t rowb = (((size_t)b * H_ + (n >> 6)) * S_ + s) << 6;
                    C[rowb + pcol(n & 63)]       = v0;
                    C[rowb + pcol((n + 1) & 63)] = v1;
                } else if (MODE == 4) {
                    v0 = f2tf_f(v0 + bias[n]);
                    v1 = f2tf_f(v1 + bias[n + 1]);
                    int b = m >> 11, s = m & (S_ - 1), h = n >> 6, hd = n & 63;
                    *reinterpret_cast<float2*>(
                        &C[((((size_t)b * H_ + h) * S_ + s) << 6) + hd]) =
                        make_float2(v0, v1);
                } else if (MODE == 2) {
                    *reinterpret_cast<float2*>(
                        &C[(size_t)z * S_ * S_ + (size_t)m * S_ + n]) =
                        make_float2(v0, v1);
                } else {
                    int b = z >> 4, h = z & 15;
                    size_t rowb = ((size_t)(b * S_ + m)) * D_ + h * HD_;
                    C[rowb + pcol(n)]     = f2tf_f(v0);
                    C[rowb + pcol(n + 1)] = f2tf_f(v1);
                }
            }
        }
    }
}

// ---------------- softmax; output tf32-rounded + column-permuted -------------
__global__ __launch_bounds__(256) void softmax_kernel(float* __restrict__ sc)
{
    __shared__ float red[8];
    const int tid = threadIdx.x;
    float* row = sc + (size_t)blockIdx.x * S_;
    const int pofs = (tid & ~7) | (((tid & 3) << 1) | ((tid >> 2) & 1));

    float v[8];
    float mx = -1e30f;
    #pragma unroll
    for (int i = 0; i < 8; i++) {
        v[i] = row[i * 256 + tid];
        mx = fmaxf(mx, v[i]);
    }
    #pragma unroll
    for (int o = 16; o > 0; o >>= 1) mx = fmaxf(mx, __shfl_xor_sync(~0u, mx, o));
    if ((tid & 31) == 0) red[tid >> 5] = mx;
    __syncthreads();
    mx = red[0];
    #pragma unroll
    for (int w = 1; w < 8; w++) mx = fmaxf(mx, red[w]);
    __syncthreads();

    float sum = 0.0f;
    #pragma unroll
    for (int i = 0; i < 8; i++) {
        v[i] = expf(v[i] - mx);
        sum += v[i];
    }
    #pragma unroll
    for (int o = 16; o > 0; o >>= 1) sum += __shfl_xor_sync(~0u, sum, o);
    if ((tid & 31) == 0) red[tid >> 5] = sum;
    __syncthreads();
    sum = 0.0f;
    #pragma unroll
    for (int w = 0; w < 8; w++) sum += red[w];
    float inv = 1.0f / sum;
    #pragma unroll
    for (int i = 0; i < 8; i++) row[i * 256 + pofs] = f2tf_f(v[i] * inv);
}

// ---------------- host launch sequence ---------------------------------------
extern "C" void kernel_launch(void* const* d_in, const int* in_sizes, int n_in,
                              void* d_out, int out_size)
{
    (void)in_sizes; (void)n_in; (void)out_size;

    const float* x     = (const float*)d_in[0];
    const float* rel   = (const float*)d_in[1];
    const float* alpha = (const float*)d_in[2];
    const float* Wq    = (const float*)d_in[3];
    const float* bq    = (const float*)d_in[4];
    const float* Wk    = (const float*)d_in[5];
    const float* bk    = (const float*)d_in[6];
    const float* Wv    = (const float*)d_in[7];
    const float* bv    = (const float*)d_in[8];
    const float* Wo    = (const float*)d_in[9];
    const float* bo    = (const float*)d_in[10];
    float* out = (float*)d_out;

    void* p;
    cudaGetSymbolAddress(&p, g_xpe);    float* xpe    = (float*)p;
    cudaGetSymbolAddress(&p, g_q);      float* q      = (float*)p;
    cudaGetSymbolAddress(&p, g_k);      float* k      = (float*)p;
    cudaGetSymbolAddress(&p, g_v);      float* v      = (float*)p;
    cudaGetSymbolAddress(&p, g_ctx);    float* ctx    = (float*)p;
    cudaGetSymbolAddress(&p, g_scores); float* scores = (float*)p;
    cudaGetSymbolAddress(&p, g_w);      float* w      = (float*)p;
    float* wq = w;
    float* wk = w + (size_t)D_ * D_;
    float* wv = w + (size_t)2 * D_ * D_;
    float* wo = w + (size_t)3 * D_ * D_;

    const int SMEM_BIG = 3 * (128 * 24 + 128 * 24) * 4;  // 73728
    const int SMEM_PV  = 3 * (128 * 24 + 64 * 24) * 4;   // 55296
    cudaFuncSetAttribute(mma_gemm<0>, cudaFuncAttributeMaxDynamicSharedMemorySize, SMEM_BIG);
    cudaFuncSetAttribute(mma_gemm<1>, cudaFuncAttributeMaxDynamicSharedMemorySize, SMEM_BIG);
    cudaFuncSetAttribute(mma_gemm<4>, cudaFuncAttributeMaxDynamicSharedMemorySize, SMEM_BIG);
    cudaFuncSetAttribute(mma_gemm<2>, cudaFuncAttributeMaxDynamicSharedMemorySize, SMEM_BIG);
    cudaFuncSetAttribute(mma_gemm<3>, cudaFuncAttributeMaxDynamicSharedMemorySize, SMEM_PV);

    // 0) weight prep (round + permute K dim), all 4 in one launch
    wprep_kernel<<<dim3(1024, 4), 256>>>(Wq, Wk, Wv, Wo);

    // 1) positional encoding (round + permute)
    pe_kernel<<<M_, 256>>>(x, rel, alpha, xpe);

    // 2) Q/K/V projections
    dim3 gproj(D_ / 128, M_ / 128, 1);
    mma_gemm<1><<<gproj, 128, SMEM_BIG>>>(xpe, wq, bq, q, 1.0f);
    mma_gemm<1><<<gproj, 128, SMEM_BIG>>>(xpe, wk, bk, k, 1.0f);
    mma_gemm<4><<<gproj, 128, SMEM_BIG>>>(xpe, wv, bv, v, 1.0f);

    // 3) scores = Q K^T / 32
    dim3 gqk(S_ / 128, S_ / 128, BH_);
    mma_gemm<2><<<gqk, 128, SMEM_BIG>>>(q, k, nullptr, scores, 0.03125f);

    // 4) softmax (+ round/permute for PV)
    softmax_kernel<<<BH_ * S_, 256>>>(scores);

    // 5) ctx = P V
    dim3 gpv(1, S_ / 128, BH_);
    mma_gemm<3><<<gpv, 128, SMEM_PV>>>(scores, v, nullptr, ctx, 1.0f);

    // 6) output projection
    mma_gemm<0><<<gproj, 128, SMEM_BIG>>>(ctx, wo, bo, out, 1.0f);
}

// round 7
// speedup vs baseline: 1.8220x; 1.8220x over previous
#include <cuda_runtime.h>
#include <cuda_fp16.h>
#include <math.h>
#include <cstdint>

#define B_  2
#define S_  2048
#define D_  1024
#define H_  16
#define HD_ 64
#define M_  (B_ * S_)
#define BH_ (B_ * H_)
#define MAXLEN_ 5000

// ---------------- scratch (device globals) ----------------------------------
__device__ __half g_xpe[M_ * D_];
__device__ __half g_q[M_ * D_];
__device__ __half g_k[M_ * D_];
__device__ __half g_vt[(size_t)BH_ * HD_ * S_];     // V transposed [z][hd][s]
__device__ __half g_ctx[M_ * D_];
__device__ float  g_scores[(size_t)BH_ * S_ * S_];  // fp32 for softmax
__device__ __half g_p[(size_t)BH_ * S_ * S_];       // fp16 attention weights
__device__ __half g_w[4][D_ * D_];

// ---------------- helpers ----------------------------------------------------
__device__ __forceinline__ uint32_t smem_u32(const void* p) {
    uint32_t a;
    asm("{ .reg .u64 t; cvta.to.shared.u64 t, %1; cvt.u32.u64 %0, t; }"
        : "=r"(a) : "l"(p));
    return a;
}
// fragment-pair permutation within 16: k -> 4*((k>>1)&3) + 2*((k>>3)&1) + (k&1)
__device__ __forceinline__ int pk16(int k) {
    return (k & ~15) | (((k >> 1) & 3) << 2) | (((k >> 3) & 1) << 1) | (k & 1);
}
__device__ __forceinline__ void mma16(float* c, const uint32_t* a, const uint32_t* b) {
    asm volatile(
        "mma.sync.aligned.m16n8k16.row.col.f32.f16.f16.f32 "
        "{%0,%1,%2,%3}, {%4,%5,%6,%7}, {%8,%9}, {%0,%1,%2,%3};"
        : "+f"(c[0]), "+f"(c[1]), "+f"(c[2]), "+f"(c[3])
        : "r"(a[0]), "r"(a[1]), "r"(a[2]), "r"(a[3]), "r"(b[0]), "r"(b[1]));
}
#define CP16(dst, src) \
    asm volatile("cp.async.cg.shared.global [%0], [%1], 16;" \
        :: "r"(dst), "l"(src) : "memory")
#define CP_COMMIT() asm volatile("cp.async.commit_group;" ::: "memory")

// ---------------- weight prep: fp16 + k-permute, all 4 weights ---------------
__global__ __launch_bounds__(256) void wprep_kernel(
    const float* __restrict__ w0, const float* __restrict__ w1,
    const float* __restrict__ w2, const float* __restrict__ w3)
{
    const float* srcs[4] = {w0, w1, w2, w3};
    const float* src = srcs[blockIdx.y];
    __half* dst = g_w[blockIdx.y];
    int base = (blockIdx.x * 256 + threadIdx.x) * 16;       // one 16-k group
    float in[16];
    #pragma unroll
    for (int j = 0; j < 16; j++) in[j] = src[base + j];
    #pragma unroll
    for (int j = 0; j < 16; j += 2) {
        int p = (((j >> 1) & 3) << 2) | (((j >> 3) & 1) << 1);
        *reinterpret_cast<__half2*>(&dst[base + p]) =
            __halves2half2(__float2half_rn(in[j]), __float2half_rn(in[j + 1]));
    }
}

// ---------------- kernel 1: x + PE -> fp16, k-permuted -----------------------
__global__ __launch_bounds__(256) void pe_kernel(
    const float* __restrict__ x, const float* __restrict__ rel,
    const float* __restrict__ alpha_p, __half* __restrict__ xpe)
{
    const int bs = blockIdx.x;
    const int s  = bs & (S_ - 1);
    const float alpha = alpha_p[0];
    const float beta  = 1.0f - alpha;
    const size_t base  = (size_t)bs * D_;
    const size_t rbase = (size_t)(MAXLEN_ - S_ + s) * D_;
    const float kC = (float)(-9.210340371976184 / 1024.0);

    int d0 = threadIdx.x * 4;
    float v[4];
    #pragma unroll
    for (int t = 0; t < 2; t++) {
        int d = d0 + t * 2;
        float divv = expf((float)d * kC);
        float ang  = (float)s * divv;
        float sn, cs;
        sincosf(ang, &sn, &cs);
        v[t * 2 + 0] = x[base + d]     + alpha * sn + beta * rel[rbase + d];
        v[t * 2 + 1] = x[base + d + 1] + alpha * cs + beta * rel[rbase + d + 1];
    }
    #pragma unroll
    for (int t = 0; t < 2; t++) {
        int d = d0 + t * 2;
        *reinterpret_cast<__half2*>(&xpe[base + pk16(d)]) =
            __halves2half2(__float2half_rn(v[t * 2]), __float2half_rn(v[t * 2 + 1]));
    }
}

// ---------------- fp16 mma.sync GEMM, 4 warps x (64x64), 3-stage pipeline ----
// MODE 0: O-proj (fp32 out)   MODE 1: Q/K proj (scatter+perm fp16)
// MODE 4: V proj -> v_t transposed fp16
// MODE 2: QK^T per z (fp32 scores)   MODE 3: PV per z -> ctx (perm fp16)
template<int MODE>
__global__ __launch_bounds__(128) void mma_gemm(
    const __half* __restrict__ A, const __half* __restrict__ Bm,
    const float* __restrict__ bias, void* __restrict__ Cv, float scale)
{
    constexpr int BM = 128, BK = 32;                 // halfs
    constexpr int BN   = (MODE == 3) ? 64 : 128;
    constexpr int WN   = (MODE == 3) ? 32 : 64;
    constexpr int NF   = WN / 8;
    constexpr int KTOT = (MODE == 2) ? 64 : ((MODE == 3) ? 2048 : 1024);
    constexpr int LDA  = (MODE == 2) ? 64 : ((MODE == 3) ? 2048 : 1024);
    constexpr int LDB  = (MODE == 2) ? 64 : ((MODE == 3) ? 2048 : 1024);
    constexpr int NK   = KTOT / BK;
    constexpr int ASZ  = BM * 32;                    // halfs per stage
    constexpr int BSZ  = BN * 32;
    constexpr int STG  = ASZ + BSZ;

    extern __shared__ __align__(16) __half sm[];
    const int tid  = threadIdx.x;
    const int wid  = tid >> 5, lane = tid & 31;
    const int gid  = lane >> 2, tig = lane & 3;
    const int wm   = wid & 1;
    const int wn   = wid >> 1;

    const int bm = blockIdx.y * BM;
    const int bn = blockIdx.x * BN;
    const int z  = blockIdx.z;

    const __half* Ab = A  + ((MODE == 2) ? (size_t)z * S_ * HD_
                           : (MODE == 3) ? (size_t)z * S_ * S_ : (size_t)0);
    const __half* Bb = Bm + ((MODE == 2) ? (size_t)z * S_ * HD_
                           : (MODE == 3) ? (size_t)z * HD_ * S_ : (size_t)0);

    float acc[4][NF][4];
    #pragma unroll
    for (int i = 0; i < 4; i++)
        #pragma unroll
        for (int j = 0; j < NF; j++)
            #pragma unroll
            for (int r = 0; r < 4; r++) acc[i][j][r] = 0.0f;

    auto load_stage = [&](int kc, int buf) {
        __half* sA = sm + buf * STG;
        __half* sB = sA + ASZ;
        const __half* Ap = Ab + (size_t)bm * LDA + kc * BK;
        uint32_t sAu = smem_u32(sA);
        #pragma unroll
        for (int i = 0; i < 4; i++) {
            int f = tid + i * 128;
            int m = f >> 2, c = f & 3;
            CP16(sAu + (uint32_t)(m * 32 + ((c ^ (m & 3)) << 3)) * 2,
                 Ap + (size_t)m * LDA + c * 8);
        }
        const __half* Bp = Bb + (size_t)bn * LDB + kc * BK;
        uint32_t sBu = smem_u32(sB);
        #pragma unroll
        for (int i = 0; i < BN / 32; i++) {
            int f = tid + i * 128;
            int n = f >> 2, c = f & 3;
            CP16(sBu + (uint32_t)(n * 32 + ((c ^ (n & 3)) << 3)) * 2,
                 Bp + (size_t)n * LDB + c * 8);
        }
        CP_COMMIT();
    };

    load_stage(0, 0);
    load_stage(1, 1);

    int buf = 0;
    for (int kc = 0; kc < NK; kc++) {
        asm volatile("cp.async.wait_group 1;" ::: "memory");
        __syncthreads();

        const __half* sA = sm + buf * STG;
        const __half* sB = sA + ASZ;

        #pragma unroll
        for (int kk = 0; kk < 2; kk++) {             // 2 x k16 per stage
            const int cb = kk * 2 + (tig >> 1);      // chunk index 0..3
            const int hw = (tig & 1) << 2;           // half offset within chunk
            uint32_t a[4][4];
            #pragma unroll
            for (int mf = 0; mf < 4; mf++) {
                int row = wm * 64 + mf * 16 + gid;
                int off = row * 32 + ((cb ^ (row & 3)) << 3) + hw;
                uint2 w0 = *reinterpret_cast<const uint2*>(sA + off);
                uint2 w1 = *reinterpret_cast<const uint2*>(sA + off + 8 * 32);
                a[mf][0] = w0.x; a[mf][1] = w1.x;
                a[mf][2] = w0.y; a[mf][3] = w1.y;
            }
            uint32_t b[NF][2];
            #pragma unroll
            for (int nf = 0; nf < NF; nf++) {
                int n = wn * WN + nf * 8 + gid;
                int off = n * 32 + ((cb ^ (n & 3)) << 3) + hw;
                uint2 w = *reinterpret_cast<const uint2*>(sB + off);
                b[nf][0] = w.x; b[nf][1] = w.y;
            }
            #pragma unroll
            for (int mf = 0; mf < 4; mf++)
                #pragma unroll
                for (int nf = 0; nf < NF; nf++)
                    mma16(acc[mf][nf], a[mf], b[nf]);
        }

        if (kc + 2 < NK) load_stage(kc + 2, (kc + 2) % 3);
        else             CP_COMMIT();
        buf = (buf + 1 == 3) ? 0 : buf + 1;
    }

    // ---- epilogue -----------------------------------------------------------
    #pragma unroll
    for (int mf = 0; mf < 4; mf++) {
        #pragma unroll
        for (int r = 0; r < 2; r++) {
            int m = bm + wm * 64 + mf * 16 + gid + r * 8;
            #pragma unroll
            for (int nf = 0; nf < NF; nf++) {
                int n = bn + wn * WN + nf * 8 + 2 * tig;
                float v0 = acc[mf][nf][r * 2 + 0] * scale;
                float v1 = acc[mf][nf][r * 2 + 1] * scale;
                if (MODE == 0) {
                    float* C = (float*)Cv;
                    v0 += bias[n]; v1 += bias[n + 1];
                    *reinterpret_cast<float2*>(&C[(size_t)m * D_ + n]) =
                        make_float2(v0, v1);
                } else if (MODE == 1) {
                    __half* C = (__half*)Cv;
                    v0 += bias[n]; v1 += bias[n + 1];
                    int b = m >> 11, s = m & (S_ - 1);
                    size_t rowb = (((size_t)b * H_ + (n >> 6)) * S_ + s) << 6;
                    *reinterpret_cast<__half2*>(&C[rowb + pk16(n & 63)]) =
                        __halves2half2(__float2half_rn(v0), __float2half_rn(v1));
                } else if (MODE == 4) {
                    // V -> v_t[z][hd][pk(s)] transposed scatter
                    __half* C = (__half*)Cv;
                    v0 += bias[n]; v1 += bias[n + 1];
                    int b = m >> 11, s = m & (S_ - 1), h = n >> 6, hd = n & 63;
                    size_t zb = ((size_t)(b * H_ + h) * HD_) * S_;
                    C[zb + (size_t)hd * S_ + pk16(s)]       = __float2half_rn(v0);
                    C[zb + (size_t)(hd + 1) * S_ + pk16(s)] = __float2half_rn(v1);
                } else if (MODE == 2) {
                    float* C = (float*)Cv;
                    *reinterpret_cast<float2*>(
                        &C[(size_t)z * S_ * S_ + (size_t)m * S_ + n]) =
                        make_float2(v0, v1);
                } else {
                    // ctx: fp16, column-permuted (feeds O-proj K dim)
                    __half* C = (__half*)Cv;
                    int b = z >> 4, h = z & 15;
                    size_t rowb = ((size_t)(b * S_ + m)) * D_ + h * HD_;
                    *reinterpret_cast<__half2*>(&C[rowb + pk16(n)]) =
                        __halves2half2(__float2half_rn(v0), __float2half_rn(v1));
                }
            }
        }
    }
}

// ---------------- softmax: fp32 in, fp16 k-permuted out ----------------------
__global__ __launch_bounds__(256) void softmax_kernel(
    const float* __restrict__ sc, __half* __restrict__ pout)
{
    __shared__ float red[8];
    const int tid = threadIdx.x;
    const float* row = sc + (size_t)blockIdx.x * S_;
    __half* prow = pout + (size_t)blockIdx.x * S_;
    const int pofs = pk16(tid & 15) | (tid & ~15);

    float v[8];
    float mx = -1e30f;
    #pragma unroll
    for (int i = 0; i < 8; i++) {
        v[i] = row[i * 256 + tid];
        mx = fmaxf(mx, v[i]);
    }
    #pragma unroll
    for (int o = 16; o > 0; o >>= 1) mx = fmaxf(mx, __shfl_xor_sync(~0u, mx, o));
    if ((tid & 31) == 0) red[tid >> 5] = mx;
    __syncthreads();
    mx = red[0];
    #pragma unroll
    for (int w = 1; w < 8; w++) mx = fmaxf(mx, red[w]);
    __syncthreads();

    float sum = 0.0f;
    #pragma unroll
    for (int i = 0; i < 8; i++) {
        v[i] = expf(v[i] - mx);
        sum += v[i];
    }
    #pragma unroll
    for (int o = 16; o > 0; o >>= 1) sum += __shfl_xor_sync(~0u, sum, o);
    if ((tid & 31) == 0) red[tid >> 5] = sum;
    __syncthreads();
    sum = 0.0f;
    #pragma unroll
    for (int w = 0; w < 8; w++) sum += red[w];
    float inv = 1.0f / sum;
    #pragma unroll
    for (int i = 0; i < 8; i++)
        prow[i * 256 + pofs] = __float2half_rn(v[i] * inv);
}

// ---------------- host launch sequence ---------------------------------------
extern "C" void kernel_launch(void* const* d_in, const int* in_sizes, int n_in,
                              void* d_out, int out_size)
{
    (void)in_sizes; (void)n_in; (void)out_size;

    const float* x     = (const float*)d_in[0];
    const float* rel   = (const float*)d_in[1];
    const float* alpha = (const float*)d_in[2];
    const float* Wq    = (const float*)d_in[3];
    const float* bq    = (const float*)d_in[4];
    const float* Wk    = (const float*)d_in[5];
    const float* bk    = (const float*)d_in[6];
    const float* Wv    = (const float*)d_in[7];
    const float* bv    = (const float*)d_in[8];
    const float* Wo    = (const float*)d_in[9];
    const float* bo    = (const float*)d_in[10];
    float* out = (float*)d_out;

    void* p;
    cudaGetSymbolAddress(&p, g_xpe);    __half* xpe    = (__half*)p;
    cudaGetSymbolAddress(&p, g_q);      __half* q      = (__half*)p;
    cudaGetSymbolAddress(&p, g_k);      __half* k      = (__half*)p;
    cudaGetSymbolAddress(&p, g_vt);     __half* vt     = (__half*)p;
    cudaGetSymbolAddress(&p, g_ctx);    __half* ctx    = (__half*)p;
    cudaGetSymbolAddress(&p, g_scores); float*  scores = (float*)p;
    cudaGetSymbolAddress(&p, g_p);      __half* pmat   = (__half*)p;
    cudaGetSymbolAddress(&p, g_w);      __half* w      = (__half*)p;
    __half* wq = w;
    __half* wk = w + (size_t)D_ * D_;
    __half* wv = w + (size_t)2 * D_ * D_;
    __half* wo = w + (size_t)3 * D_ * D_;

    const int SMEM_BIG = 3 * (128 * 32 + 128 * 32) * 2;  // 49152
    const int SMEM_PV  = 3 * (128 * 32 + 64 * 32) * 2;   // 36864
    cudaFuncSetAttribute(mma_gemm<0>, cudaFuncAttributeMaxDynamicSharedMemorySize, SMEM_BIG);
    cudaFuncSetAttribute(mma_gemm<1>, cudaFuncAttributeMaxDynamicSharedMemorySize, SMEM_BIG);
    cudaFuncSetAttribute(mma_gemm<4>, cudaFuncAttributeMaxDynamicSharedMemorySize, SMEM_BIG);
    cudaFuncSetAttribute(mma_gemm<2>, cudaFuncAttributeMaxDynamicSharedMemorySize, SMEM_BIG);
    cudaFuncSetAttribute(mma_gemm<3>, cudaFuncAttributeMaxDynamicSharedMemorySize, SMEM_PV);

    // 0) weight prep (fp16 + permute), all 4 in one launch
    wprep_kernel<<<dim3(256, 4), 256>>>(Wq, Wk, Wv, Wo);

    // 1) positional encoding
    pe_kernel<<<M_, 256>>>(x, rel, alpha, xpe);

    // 2) Q/K/V projections
    dim3 gproj(D_ / 128, M_ / 128, 1);
    mma_gemm<1><<<gproj, 128, SMEM_BIG>>>(xpe, wq, bq, q, 1.0f);
    mma_gemm<1><<<gproj, 128, SMEM_BIG>>>(xpe, wk, bk, k, 1.0f);
    mma_gemm<4><<<gproj, 128, SMEM_BIG>>>(xpe, wv, bv, vt, 1.0f);

    // 3) scores = Q K^T / 32  (fp32)
    dim3 gqk(S_ / 128, S_ / 128, BH_);
    mma_gemm<2><<<gqk, 128, SMEM_BIG>>>(q, k, nullptr, scores, 0.03125f);

    // 4) softmax -> fp16 P (k-permuted)
    softmax_kernel<<<BH_ * S_, 256>>>(scores, pmat);

    // 5) ctx = P V  (B = pre-transposed v_t)
    dim3 gpv(1, S_ / 128, BH_);
    mma_gemm<3><<<gpv, 128, SMEM_PV>>>(pmat, vt, nullptr, ctx, 1.0f);

    // 6) output projection (fp32 out)
    mma_gemm<0><<<gproj, 128, SMEM_BIG>>>(ctx, wo, bo, out, 1.0f);
}

// round 8
// speedup vs baseline: 3.0579x; 1.6783x over previous
#include <cuda_runtime.h>
#include <cuda_fp16.h>
#include <math.h>
#include <cstdint>

#define B_  2
#define S_  2048
#define D_  1024
#define H_  16
#define HD_ 64
#define M_  (B_ * S_)
#define BH_ (B_ * H_)
#define MAXLEN_ 5000

// ---------------- scratch (device globals) ----------------------------------
__device__ __half g_xpe[M_ * D_];
__device__ __half g_q[M_ * D_];                      // pre-scaled by 1/32
__device__ __half g_k[M_ * D_];
__device__ __half g_vt[(size_t)BH_ * HD_ * S_];      // V transposed [z][hd][s]
__device__ __half g_ctx[M_ * D_];
__device__ __half g_w[4][D_ * D_];

// ---------------- helpers ----------------------------------------------------
__device__ __forceinline__ uint32_t smem_u32(const void* p) {
    uint32_t a;
    asm("{ .reg .u64 t; cvta.to.shared.u64 t, %1; cvt.u32.u64 %0, t; }"
        : "=r"(a) : "l"(p));
    return a;
}
// fragment-pair permutation within 16: k -> 4*((k>>1)&3) + 2*((k>>3)&1) + (k&1)
__device__ __forceinline__ int pk16(int k) {
    return (k & ~15) | (((k >> 1) & 3) << 2) | (((k >> 3) & 1) << 1) | (k & 1);
}
__device__ __forceinline__ void mma16(float* c, const uint32_t* a, const uint32_t* b) {
    asm volatile(
        "mma.sync.aligned.m16n8k16.row.col.f32.f16.f16.f32 "
        "{%0,%1,%2,%3}, {%4,%5,%6,%7}, {%8,%9}, {%0,%1,%2,%3};"
        : "+f"(c[0]), "+f"(c[1]), "+f"(c[2]), "+f"(c[3])
        : "r"(a[0]), "r"(a[1]), "r"(a[2]), "r"(a[3]), "r"(b[0]), "r"(b[1]));
}
__device__ __forceinline__ uint32_t h2pack(float a, float b) {
    uint32_t r;
    asm("cvt.rn.f16x2.f32 %0, %2, %1;" : "=r"(r) : "f"(a), "f"(b));
    return r;
}
#define CP16(dst, src) \
    asm volatile("cp.async.cg.shared.global [%0], [%1], 16;" \
        :: "r"(dst), "l"(src) : "memory")
#define CP_COMMIT() asm volatile("cp.async.commit_group;" ::: "memory")

// ---------------- weight prep: fp16 + k-permute, all 4 weights ---------------
__global__ __launch_bounds__(256) void wprep_kernel(
    const float* __restrict__ w0, const float* __restrict__ w1,
    const float* __restrict__ w2, const float* __restrict__ w3)
{
    const float* srcs[4] = {w0, w1, w2, w3};
    const float* src = srcs[blockIdx.y];
    __half* dst = g_w[blockIdx.y];
    int base = (blockIdx.x * 256 + threadIdx.x) * 16;
    float in[16];
    #pragma unroll
    for (int j = 0; j < 16; j++) in[j] = src[base + j];
    #pragma unroll
    for (int j = 0; j < 16; j += 2) {
        int p = (((j >> 1) & 3) << 2) | (((j >> 3) & 1) << 1);
        *reinterpret_cast<__half2*>(&dst[base + p]) =
            __halves2half2(__float2half_rn(in[j]), __float2half_rn(in[j + 1]));
    }
}

// ---------------- kernel 1: x + PE -> fp16, k-permuted -----------------------
__global__ __launch_bounds__(256) void pe_kernel(
    const float* __restrict__ x, const float* __restrict__ rel,
    const float* __restrict__ alpha_p, __half* __restrict__ xpe)
{
    const int bs = blockIdx.x;
    const int s  = bs & (S_ - 1);
    const float alpha = alpha_p[0];
    const float beta  = 1.0f - alpha;
    const size_t base  = (size_t)bs * D_;
    const size_t rbase = (size_t)(MAXLEN_ - S_ + s) * D_;
    const float kC = (float)(-9.210340371976184 / 1024.0);

    int d0 = threadIdx.x * 4;
    float v[4];
    #pragma unroll
    for (int t = 0; t < 2; t++) {
        int d = d0 + t * 2;
        float divv = expf((float)d * kC);
        float ang  = (float)s * divv;
        float sn, cs;
        sincosf(ang, &sn, &cs);
        v[t * 2 + 0] = x[base + d]     + alpha * sn + beta * rel[rbase + d];
        v[t * 2 + 1] = x[base + d + 1] + alpha * cs + beta * rel[rbase + d + 1];
    }
    #pragma unroll
    for (int t = 0; t < 2; t++) {
        int d = d0 + t * 2;
        *reinterpret_cast<__half2*>(&xpe[base + pk16(d)]) =
            __halves2half2(__float2half_rn(v[t * 2]), __float2half_rn(v[t * 2 + 1]));
    }
}

// ---------------- fp16 mma.sync projection GEMM ------------------------------
// MODE 0: O-proj (fp32 out)  MODE 1: Q/K proj (scatter+perm, (acc+bias)*scale)
// MODE 4: V proj -> v_t transposed fp16
template<int MODE>
__global__ __launch_bounds__(128) void mma_gemm(
    const __half* __restrict__ A, const __half* __restrict__ Bm,
    const float* __restrict__ bias, void* __restrict__ Cv, float scale)
{
    constexpr int BM = 128, BK = 32, BN = 128, WN = 64, NF = WN / 8;
    constexpr int KTOT = 1024, LDA = 1024, LDB = 1024;
    constexpr int NK   = KTOT / BK;
    constexpr int ASZ  = BM * 32;
    constexpr int BSZ  = BN * 32;
    constexpr int STG  = ASZ + BSZ;

    extern __shared__ __align__(16) __half sm[];
    const int tid  = threadIdx.x;
    const int wid  = tid >> 5, lane = tid & 31;
    const int gid  = lane >> 2, tig = lane & 3;
    const int wm   = wid & 1;
    const int wn   = wid >> 1;

    const int bm = blockIdx.y * BM;
    const int bn = blockIdx.x * BN;

    float acc[4][NF][4];
    #pragma unroll
    for (int i = 0; i < 4; i++)
        #pragma unroll
        for (int j = 0; j < NF; j++)
            #pragma unroll
            for (int r = 0; r < 4; r++) acc[i][j][r] = 0.0f;

    auto load_stage = [&](int kc, int buf) {
        __half* sA = sm + buf * STG;
        __half* sB = sA + ASZ;
        const __half* Ap = A + (size_t)bm * LDA + kc * BK;
        uint32_t sAu = smem_u32(sA);
        #pragma unroll
        for (int i = 0; i < 4; i++) {
            int f = tid + i * 128;
            int m = f >> 2, c = f & 3;
            CP16(sAu + (uint32_t)(m * 32 + ((c ^ (m & 3)) << 3)) * 2,
                 Ap + (size_t)m * LDA + c * 8);
        }
        const __half* Bp = Bm + (size_t)bn * LDB + kc * BK;
        uint32_t sBu = smem_u32(sB);
        #pragma unroll
        for (int i = 0; i < 4; i++) {
            int f = tid + i * 128;
            int n = f >> 2, c = f & 3;
            CP16(sBu + (uint32_t)(n * 32 + ((c ^ (n & 3)) << 3)) * 2,
                 Bp + (size_t)n * LDB + c * 8);
        }
        CP_COMMIT();
    };

    load_stage(0, 0);
    load_stage(1, 1);

    int buf = 0;
    for (int kc = 0; kc < NK; kc++) {
        asm volatile("cp.async.wait_group 1;" ::: "memory");
        __syncthreads();

        const __half* sA = sm + buf * STG;
        const __half* sB = sA + ASZ;

        #pragma unroll
        for (int kk = 0; kk < 2; kk++) {
            const int cb = kk * 2 + (tig >> 1);
            const int hw = (tig & 1) << 2;
            uint32_t a[4][4];
            #pragma unroll
            for (int mf = 0; mf < 4; mf++) {
                int row = wm * 64 + mf * 16 + gid;
                int off = row * 32 + ((cb ^ (row & 3)) << 3) + hw;
                uint2 w0 = *reinterpret_cast<const uint2*>(sA + off);
                uint2 w1 = *reinterpret_cast<const uint2*>(sA + off + 8 * 32);
                a[mf][0] = w0.x; a[mf][1] = w1.x;
                a[mf][2] = w0.y; a[mf][3] = w1.y;
            }
            uint32_t b[NF][2];
            #pragma unroll
            for (int nf = 0; nf < NF; nf++) {
                int n = wn * WN + nf * 8 + gid;
                int off = n * 32 + ((cb ^ (n & 3)) << 3) + hw;
                uint2 w = *reinterpret_cast<const uint2*>(sB + off);
                b[nf][0] = w.x; b[nf][1] = w.y;
            }
            #pragma unroll
            for (int mf = 0; mf < 4; mf++)
                #pragma unroll
                for (int nf = 0; nf < NF; nf++)
                    mma16(acc[mf][nf], a[mf], b[nf]);
        }

        if (kc + 2 < NK) load_stage(kc + 2, (kc + 2) % 3);
        else             CP_COMMIT();
        buf = (buf + 1 == 3) ? 0 : buf + 1;
    }

    #pragma unroll
    for (int mf = 0; mf < 4; mf++) {
        #pragma unroll
        for (int r = 0; r < 2; r++) {
            int m = bm + wm * 64 + mf * 16 + gid + r * 8;
            #pragma unroll
            for (int nf = 0; nf < NF; nf++) {
                int n = bn + wn * WN + nf * 8 + 2 * tig;
                float v0 = acc[mf][nf][r * 2 + 0];
                float v1 = acc[mf][nf][r * 2 + 1];
                if (MODE == 0) {
                    float* C = (float*)Cv;
                    v0 += bias[n]; v1 += bias[n + 1];
                    *reinterpret_cast<float2*>(&C[(size_t)m * D_ + n]) =
                        make_float2(v0, v1);
                } else if (MODE == 1) {
                    __half* C = (__half*)Cv;
                    v0 = (v0 + bias[n]) * scale;
                    v1 = (v1 + bias[n + 1]) * scale;
                    int b = m >> 11, s = m & (S_ - 1);
                    size_t rowb = (((size_t)b * H_ + (n >> 6)) * S_ + s) << 6;
                    *reinterpret_cast<__half2*>(&C[rowb + pk16(n & 63)]) =
                        __halves2half2(__float2half_rn(v0), __float2half_rn(v1));
                } else {
                    // V -> v_t[z][hd][pk(s)] transposed scatter
                    __half* C = (__half*)Cv;
                    v0 += bias[n]; v1 += bias[n + 1];
                    int b = m >> 11, s = m & (S_ - 1), h = n >> 6, hd = n & 63;
                    size_t zb = ((size_t)(b * H_ + h) * HD_) * S_;
                    C[zb + (size_t)hd * S_ + pk16(s)]       = __float2half_rn(v0);
                    C[zb + (size_t)(hd + 1) * S_ + pk16(s)] = __float2half_rn(v1);
                }
            }
        }
    }
}

// ---------------- fused flash attention --------------------------------------
// grid (16 q-tiles, 32 z). 128 threads, warp owns 32 q-rows x full hd=64.
// Q pre-scaled by 1/32. K smem [key][hd], V smem [hd][key] (both pair-permuted).
__global__ __launch_bounds__(128) void flash_kernel(
    const __half* __restrict__ Q, const __half* __restrict__ K,
    const __half* __restrict__ Vt, __half* __restrict__ ctx)
{
    // smem halfs: sQ[8192] | sK[2][4096] | sV[2][4096]  (two 32-half subtiles each)
    extern __shared__ __align__(16) __half sm[];
    __half* sQ = sm;
    __half* sKb = sm + 8192;
    __half* sVb = sm + 16384;

    const int tid = threadIdx.x;
    const int wid = tid >> 5, lane = tid & 31;
    const int gid = lane >> 2, tig = lane & 3;
    const int qt = blockIdx.x, z = blockIdx.y;

    const __half* Qz = Q  + (size_t)z * S_ * HD_ + (size_t)qt * 128 * HD_;
    const __half* Kz = K  + (size_t)z * S_ * HD_;
    const __half* Vz = Vt + (size_t)z * HD_ * S_;

    // ---- loaders ----
    auto kvld = [&](int j, int buf) {
        uint32_t sKu = smem_u32(sKb + buf * 4096);
        uint32_t sVu = smem_u32(sVb + buf * 4096);
        #pragma unroll
        for (int i = 0; i < 4; i++) {
            int idx = tid + i * 128;
            int row = idx >> 3, c = idx & 7;
            uint32_t off = (uint32_t)((c >> 2) * 2048 + row * 32 +
                                      (((c & 3) ^ (row & 3)) << 3)) * 2;
            CP16(sKu + off, Kz + (size_t)(j * 64 + row) * HD_ + c * 8);
            CP16(sVu + off, Vz + (size_t)row * S_ + j * 64 + c * 8);
        }
    };
    {   // Q + first K/V tile in group 0
        uint32_t sQu = smem_u32(sQ);
        #pragma unroll
        for (int i = 0; i < 8; i++) {
            int idx = tid + i * 128;
            int row = idx >> 3, c = idx & 7;
            CP16(sQu + (uint32_t)((c >> 2) * 4096 + row * 32 +
                                  (((c & 3) ^ (row & 3)) << 3)) * 2,
                 Qz + (size_t)row * HD_ + c * 8);
        }
        kvld(0, 0);
        CP_COMMIT();
        kvld(1, 1);
        CP_COMMIT();
    }
    asm volatile("cp.async.wait_group 1;" ::: "memory");
    __syncthreads();

    // ---- Q fragments to registers (rows wid*32 + mf*16 + gid, +8) ----
    uint32_t qf[2][4][4];
    #pragma unroll
    for (int mf = 0; mf < 2; mf++) {
        #pragma unroll
        for (int kb = 0; kb < 4; kb++) {
            int row = wid * 32 + mf * 16 + gid;
            int cb  = (kb & 1) * 2 + (tig >> 1);
            int hw  = (tig & 1) << 2;
            int sub = (kb >> 1) * 4096;
            uint2 w0 = *reinterpret_cast<const uint2*>(
                sQ + sub + row * 32 + ((cb ^ (row & 3)) << 3) + hw);
            uint2 w1 = *reinterpret_cast<const uint2*>(
                sQ + sub + (row + 8) * 32 + ((cb ^ ((row + 8) & 3)) << 3) + hw);
            qf[mf][kb][0] = w0.x; qf[mf][kb][1] = w1.x;
            qf[mf][kb][2] = w0.y; qf[mf][kb][3] = w1.y;
        }
    }

    float oacc[2][8][4];
    #pragma unroll
    for (int mf = 0; mf < 2; mf++)
        #pragma unroll
        for (int nf = 0; nf < 8; nf++)
            #pragma unroll
            for (int r = 0; r < 4; r++) oacc[mf][nf][r] = 0.0f;
    float mrow[2][2] = {{-1e30f, -1e30f}, {-1e30f, -1e30f}};
    float lrow[2][2] = {{0.0f, 0.0f}, {0.0f, 0.0f}};

    for (int j = 0; j < 32; j++) {
        const int buf = j & 1;
        const __half* sK = sKb + buf * 4096;
        const __half* sV = sVb + buf * 4096;

        // ---- S = Q K^T (pre-scaled) ----
        float sacc[2][8][4];
        #pragma unroll
        for (int mf = 0; mf < 2; mf++)
            #pragma unroll
            for (int nf = 0; nf < 8; nf++)
                #pragma unroll
                for (int r = 0; r < 4; r++) sacc[mf][nf][r] = 0.0f;
        #pragma unroll
        for (int kb = 0; kb < 4; kb++) {
            const int cb = (kb & 1) * 2 + (tig >> 1);
            const int hw = (tig & 1) << 2;
            const int sub = (kb >> 1) * 2048;
            #pragma unroll
            for (int nf = 0; nf < 8; nf++) {
                int rk = nf * 8 + gid;
                uint2 w = *reinterpret_cast<const uint2*>(
                    sK + sub + rk * 32 + ((cb ^ (rk & 3)) << 3) + hw);
                uint32_t b[2] = {w.x, w.y};
                mma16(sacc[0][nf], qf[0][kb], b);
                mma16(sacc[1][nf], qf[1][kb], b);
            }
        }

        // ---- online softmax ----
        float alpha[2][2];
        #pragma unroll
        for (int mf = 0; mf < 2; mf++) {
            #pragma unroll
            for (int rr = 0; rr < 2; rr++) {
                float mx = -1e30f;
                #pragma unroll
                for (int nf = 0; nf < 8; nf++) {
                    mx = fmaxf(mx, sacc[mf][nf][rr * 2]);
                    mx = fmaxf(mx, sacc[mf][nf][rr * 2 + 1]);
                }
                mx = fmaxf(mx, __shfl_xor_sync(~0u, mx, 1));
                mx = fmaxf(mx, __shfl_xor_sync(~0u, mx, 2));
                float mn = fmaxf(mrow[mf][rr], mx);
                alpha[mf][rr] = __expf(mrow[mf][rr] - mn);
                mrow[mf][rr] = mn;
            }
        }
        float rs[2][2] = {{0.0f, 0.0f}, {0.0f, 0.0f}};
        #pragma unroll
        for (int mf = 0; mf < 2; mf++)
            #pragma unroll
            for (int nf = 0; nf < 8; nf++)
                #pragma unroll
                for (int rr = 0; rr < 2; rr++) {
                    float e0 = __expf(sacc[mf][nf][rr * 2]     - mrow[mf][rr]);
                    float e1 = __expf(sacc[mf][nf][rr * 2 + 1] - mrow[mf][rr]);
                    sacc[mf][nf][rr * 2]     = e0;
                    sacc[mf][nf][rr * 2 + 1] = e1;
                    rs[mf][rr] += e0 + e1;
                }
        #pragma unroll
        for (int mf = 0; mf < 2; mf++)
            #pragma unroll
            for (int rr = 0; rr < 2; rr++) {
                float s = rs[mf][rr];
                s += __shfl_xor_sync(~0u, s, 1);
                s += __shfl_xor_sync(~0u, s, 2);
                lrow[mf][rr] = lrow[mf][rr] * alpha[mf][rr] + s;
            }

        // ---- rescale O, pack P to fp16 A-fragments ----
        #pragma unroll
        for (int mf = 0; mf < 2; mf++)
            #pragma unroll
            for (int nf = 0; nf < 8; nf++) {
                oacc[mf][nf][0] *= alpha[mf][0];
                oacc[mf][nf][1] *= alpha[mf][0];
                oacc[mf][nf][2] *= alpha[mf][1];
                oacc[mf][nf][3] *= alpha[mf][1];
            }
        uint32_t ph[2][4][4];
        #pragma unroll
        for (int mf = 0; mf < 2; mf++)
            #pragma unroll
            for (int kb = 0; kb < 4; kb++) {
                ph[mf][kb][0] = h2pack(sacc[mf][2 * kb][0],     sacc[mf][2 * kb][1]);
                ph[mf][kb][1] = h2pack(sacc[mf][2 * kb][2],     sacc[mf][2 * kb][3]);
                ph[mf][kb][2] = h2pack(sacc[mf][2 * kb + 1][0], sacc[mf][2 * kb + 1][1]);
                ph[mf][kb][3] = h2pack(sacc[mf][2 * kb + 1][2], sacc[mf][2 * kb + 1][3]);
            }

        // ---- O += P V ----
        #pragma unroll
        for (int kb = 0; kb < 4; kb++) {
            const int cb = (kb & 1) * 2 + (tig >> 1);
            const int hw = (tig & 1) << 2;
            const int sub = (kb >> 1) * 2048;
            #pragma unroll
            for (int nf = 0; nf < 8; nf++) {
                int rv = nf * 8 + gid;
                uint2 w = *reinterpret_cast<const uint2*>(
                    sV + sub + rv * 32 + ((cb ^ (rv & 3)) << 3) + hw);
                uint32_t b[2] = {w.x, w.y};
                mma16(oacc[0][nf], ph[0][kb], b);
                mma16(oacc[1][nf], ph[1][kb], b);
            }
        }

        __syncthreads();                      // all warps done with buf
        if (j + 2 < 32) kvld(j + 2, buf);
        CP_COMMIT();
        if (j + 1 < 32) {
            asm volatile("cp.async.wait_group 1;" ::: "memory");
            __syncthreads();
        }
    }

    // ---- epilogue: O / l -> ctx fp16, column-permuted -----------------------
    const int b = z >> 4, h = z & 15;
    #pragma unroll
    for (int mf = 0; mf < 2; mf++) {
        #pragma unroll
        for (int rr = 0; rr < 2; rr++) {
            int m = qt * 128 + wid * 32 + mf * 16 + gid + rr * 8;
            float inv = 1.0f / lrow[mf][rr];
            size_t rowb = ((size_t)(b * S_ + m)) * D_ + h * HD_;
            #pragma unroll
            for (int nf = 0; nf < 8; nf++) {
                int n = nf * 8 + 2 * tig;
                float v0 = oacc[mf][nf][rr * 2]     * inv;
                float v1 = oacc[mf][nf][rr * 2 + 1] * inv;
                *reinterpret_cast<__half2*>(&ctx[rowb + pk16(n)]) =
                    __halves2half2(__float2half_rn(v0), __float2half_rn(v1));
            }
        }
    }
}

// ---------------- host launch sequence ---------------------------------------
extern "C" void kernel_launch(void* const* d_in, const int* in_sizes, int n_in,
                              void* d_out, int out_size)
{
    (void)in_sizes; (void)n_in; (void)out_size;

    const float* x     = (const float*)d_in[0];
    const float* rel   = (const float*)d_in[1];
    const float* alpha = (const float*)d_in[2];
    const float* Wq    = (const float*)d_in[3];
    const float* bq    = (const float*)d_in[4];
    const float* Wk    = (const float*)d_in[5];
    const float* bk    = (const float*)d_in[6];
    const float* Wv    = (const float*)d_in[7];
    const float* bv    = (const float*)d_in[8];
    const float* Wo    = (const float*)d_in[9];
    const float* bo    = (const float*)d_in[10];
    float* out = (float*)d_out;

    void* p;
    cudaGetSymbolAddress(&p, g_xpe);    __half* xpe    = (__half*)p;
    cudaGetSymbolAddress(&p, g_q);      __half* q      = (__half*)p;
    cudaGetSymbolAddress(&p, g_k);      __half* k      = (__half*)p;
    cudaGetSymbolAddress(&p, g_vt);     __half* vt     = (__half*)p;
    cudaGetSymbolAddress(&p, g_ctx);    __half* ctx    = (__half*)p;
    cudaGetSymbolAddress(&p, g_w);      __half* w      = (__half*)p;
    __half* wq = w;
    __half* wk = w + (size_t)D_ * D_;
    __half* wv = w + (size_t)2 * D_ * D_;
    __half* wo = w + (size_t)3 * D_ * D_;

    const int SMEM_BIG = 3 * (128 * 32 + 128 * 32) * 2;  // 49152
    const int SMEM_FL  = (8192 + 8192 + 8192) * 2;       // 49152
    cudaFuncSetAttribute(mma_gemm<0>, cudaFuncAttributeMaxDynamicSharedMemorySize, SMEM_BIG);
    cudaFuncSetAttribute(mma_gemm<1>, cudaFuncAttributeMaxDynamicSharedMemorySize, SMEM_BIG);
    cudaFuncSetAttribute(mma_gemm<4>, cudaFuncAttributeMaxDynamicSharedMemorySize, SMEM_BIG);
    cudaFuncSetAttribute(flash_kernel, cudaFuncAttributeMaxDynamicSharedMemorySize, SMEM_FL);

    // 0) weight prep
    wprep_kernel<<<dim3(256, 4), 256>>>(Wq, Wk, Wv, Wo);

    // 1) positional encoding
    pe_kernel<<<M_, 256>>>(x, rel, alpha, xpe);

    // 2) Q/K/V projections (Q pre-scaled by 1/32)
    dim3 gproj(D_ / 128, M_ / 128, 1);
    mma_gemm<1><<<gproj, 128, SMEM_BIG>>>(xpe, wq, bq, q, 0.03125f);
    mma_gemm<1><<<gproj, 128, SMEM_BIG>>>(xpe, wk, bk, k, 1.0f);
    mma_gemm<4><<<gproj, 128, SMEM_BIG>>>(xpe, wv, bv, vt, 1.0f);

    // 3) fused attention -> ctx
    flash_kernel<<<dim3(S_ / 128, BH_), 128, SMEM_FL>>>(q, k, vt, ctx);

    // 4) output projection (fp32 out)
    mma_gemm<0><<<gproj, 128, SMEM_BIG>>>(ctx, wo, bo, out, 1.0f);
}